// round 2
// baseline (speedup 1.0000x reference)
#include <cuda_runtime.h>
#include <math.h>

// Problem dims (fixed by the reference)
#define SEQ   128
#define BATCH 256
#define IND   1024
#define HID   1024
#define OUTD  1024
#define G4    4096          // 4*HID
#define BH    (BATCH*HID)   // 262144

// ---------------- scratch (device globals; no runtime allocation) ----------
__device__ float g_Xp[(size_t)SEQ * BATCH * G4];   // 512 MB: X@W_ih^T + bias, per (s,b)
__device__ float g_hs[(size_t)SEQ * BATCH * HID];  // 128 MB: hidden states
__device__ float g_att[(size_t)SEQ * BATCH * HID]; // 128 MB: attention-mixed states
__device__ float g_gates[BATCH * G4];              // 4 MB: per-step gates
__device__ float g_h[BATCH * HID];
__device__ float g_c[BATCH * HID];
__device__ float g_A[SEQ * SEQ];                   // softmaxed attnW
__device__ float g_bias[G4];                       // b_ih + b_hh

// ---------------- packed f32x2 FMA (2 FMAs per issue slot on sm_103a) ------
__device__ __forceinline__ float2 ffma2(float2 a, float2 b, float2 c) {
    float2 d;
    asm("{\n\t"
        ".reg .b64 ra, rb, rc, rd;\n\t"
        "mov.b64 ra, {%2, %3};\n\t"
        "mov.b64 rb, {%4, %5};\n\t"
        "mov.b64 rc, {%6, %7};\n\t"
        "fma.rn.f32x2 rd, ra, rb, rc;\n\t"
        "mov.b64 {%0, %1}, rd;\n\t"
        "}"
        : "=f"(d.x), "=f"(d.y)
        : "f"(a.x), "f"(a.y), "f"(b.x), "f"(b.y), "f"(c.x), "f"(c.y));
    return d;
}

// ---------------- generic NT SGEMM: C[M,N] = A[M,K] @ B[N,K]^T (+D)(+bias) -
// Tiles: BM=64, BN=64, BK=16, 128 threads, 8x4 outputs/thread via f32x2 pairs.
#define BM 64
#define BN 64
#define BK 16

__global__ __launch_bounds__(128)
void sgemm_nt(const float* __restrict__ A, const float* __restrict__ B,
              const float* __restrict__ D, const float* __restrict__ bias,
              float* __restrict__ C, int M, int N, int K,
              int hasD, int hasBias)
{
    __shared__ __align__(16) float As[BK][BM + 4];
    __shared__ __align__(16) float Bs[BK][BN + 4];

    const int tid = threadIdx.x;
    const int bn0 = blockIdx.x * BN;
    const int bm0 = blockIdx.y * BM;
    const int tn = tid % 16;   // 16 threads along N, 4 cols each
    const int tm = tid / 16;   // 8 threads along M, 8 rows each

    float2 acc[4][4];
    #pragma unroll
    for (int mp = 0; mp < 4; ++mp)
        #pragma unroll
        for (int i = 0; i < 4; ++i) acc[mp][i] = make_float2(0.f, 0.f);

    for (int k0 = 0; k0 < K; k0 += BK) {
        // load A tile: 64 rows x 16 k = 256 float4, 2 per thread
        #pragma unroll
        for (int it = 0; it < 2; ++it) {
            int i = tid + it * 128;
            int row = i >> 2;
            int kq = i & 3;
            float4 v = *reinterpret_cast<const float4*>(
                &A[(size_t)(bm0 + row) * K + k0 + kq * 4]);
            As[kq * 4 + 0][row] = v.x;
            As[kq * 4 + 1][row] = v.y;
            As[kq * 4 + 2][row] = v.z;
            As[kq * 4 + 3][row] = v.w;
        }
        // load B tile (rows are N-rows of B)
        #pragma unroll
        for (int it = 0; it < 2; ++it) {
            int i = tid + it * 128;
            int row = i >> 2;
            int kq = i & 3;
            float4 v = *reinterpret_cast<const float4*>(
                &B[(size_t)(bn0 + row) * K + k0 + kq * 4]);
            Bs[kq * 4 + 0][row] = v.x;
            Bs[kq * 4 + 1][row] = v.y;
            Bs[kq * 4 + 2][row] = v.z;
            Bs[kq * 4 + 3][row] = v.w;
        }
        __syncthreads();

        #pragma unroll
        for (int k = 0; k < BK; ++k) {
            float4 a0 = *reinterpret_cast<const float4*>(&As[k][tm * 8]);
            float4 a1 = *reinterpret_cast<const float4*>(&As[k][tm * 8 + 4]);
            float4 bv = *reinterpret_cast<const float4*>(&Bs[k][tn * 4]);
            float2 a2[4] = {{a0.x, a0.y}, {a0.z, a0.w}, {a1.x, a1.y}, {a1.z, a1.w}};
            float2 bb[4] = {{bv.x, bv.x}, {bv.y, bv.y}, {bv.z, bv.z}, {bv.w, bv.w}};
            #pragma unroll
            for (int mp = 0; mp < 4; ++mp)
                #pragma unroll
                for (int i = 0; i < 4; ++i)
                    acc[mp][i] = ffma2(a2[mp], bb[i], acc[mp][i]);
        }
        __syncthreads();
    }

    #pragma unroll
    for (int mp = 0; mp < 4; ++mp) {
        int m = bm0 + tm * 8 + 2 * mp;
        #pragma unroll
        for (int i = 0; i < 4; ++i) {
            int n = bn0 + tn * 4 + i;
            float v0 = acc[mp][i].x;
            float v1 = acc[mp][i].y;
            if (hasBias) { float bvv = bias[n]; v0 += bvv; v1 += bvv; }
            if (hasD) {
                v0 += D[(size_t)m * N + n];
                v1 += D[(size_t)(m + 1) * N + n];
            }
            C[(size_t)m * N + n] = v0;
            C[(size_t)(m + 1) * N + n] = v1;
        }
    }
}

// ---------------- small helper kernels -------------------------------------
__global__ void init_state(const float* __restrict__ h0, const float* __restrict__ c0)
{
    int i = blockIdx.x * blockDim.x + threadIdx.x;
    if (i < BATCH * HID) { g_h[i] = h0[i]; g_c[i] = c0[i]; }
}

__global__ void bias_combine(const float* __restrict__ b_ih, const float* __restrict__ b_hh)
{
    int i = blockIdx.x * blockDim.x + threadIdx.x;
    if (i < G4) g_bias[i] = b_ih[i] + b_hh[i];
}

__device__ __forceinline__ float sigmoidf(float x) { return 1.0f / (1.0f + expf(-x)); }

__global__ __launch_bounds__(256)
void lstm_cell(int t)
{
    int idx = blockIdx.x * blockDim.x + threadIdx.x;  // over BATCH*HID
    int b = idx >> 10;          // /1024
    int j = idx & 1023;
    const float* g = g_gates + (size_t)b * G4;
    float gi = sigmoidf(g[j]);
    float gf = sigmoidf(g[j + HID]);
    float gg = tanhf(g[j + 2 * HID]);
    float go = sigmoidf(g[j + 3 * HID]);
    float c = gf * g_c[idx] + gi * gg;
    g_c[idx] = c;
    float h = go * tanhf(c);
    g_h[idx] = h;
    g_hs[(size_t)t * BH + idx] = h;
}

__global__ void softmax128(const float* __restrict__ W)
{
    int row = blockIdx.x;
    int t = threadIdx.x;          // 128 threads
    int lane = t & 31, warp = t >> 5;
    __shared__ float red[4];
    float v = W[row * SEQ + t];

    float m = v;
    #pragma unroll
    for (int o = 16; o > 0; o >>= 1) m = fmaxf(m, __shfl_xor_sync(0xffffffffu, m, o));
    if (lane == 0) red[warp] = m;
    __syncthreads();
    m = fmaxf(fmaxf(red[0], red[1]), fmaxf(red[2], red[3]));
    __syncthreads();

    float e = expf(v - m);
    float s = e;
    #pragma unroll
    for (int o = 16; o > 0; o >>= 1) s += __shfl_xor_sync(0xffffffffu, s, o);
    if (lane == 0) red[warp] = s;
    __syncthreads();
    s = red[0] + red[1] + red[2] + red[3];
    g_A[row * SEQ + t] = e / s;
}

// att[x, n] = sum_y A[x,y] * hs[y, n],  n in [0, BH)
// block: 32 x-rows, 128 n-cols; grid (BH/128, SEQ/32)
__global__ __launch_bounds__(128)
void attn_apply()
{
    __shared__ float Asub[32][SEQ + 1];
    const int tid = threadIdx.x;
    const int n = blockIdx.x * 128 + tid;
    const int x0 = blockIdx.y * 32;

    for (int i = tid; i < 32 * SEQ; i += 128) {
        int xx = i >> 7;     // /128
        int y = i & 127;
        Asub[xx][y] = g_A[(x0 + xx) * SEQ + y];
    }
    __syncthreads();

    float acc[32];
    #pragma unroll
    for (int xx = 0; xx < 32; ++xx) acc[xx] = 0.f;

    for (int y = 0; y < SEQ; ++y) {
        float v = g_hs[(size_t)y * BH + n];
        #pragma unroll
        for (int xx = 0; xx < 32; ++xx)
            acc[xx] = fmaf(Asub[xx][y], v, acc[xx]);
    }
    #pragma unroll
    for (int xx = 0; xx < 32; ++xx)
        g_att[(size_t)(x0 + xx) * BH + n] = acc[xx];
}

// ---------------- launch ----------------------------------------------------
extern "C" void kernel_launch(void* const* d_in, const int* in_sizes, int n_in,
                              void* d_out, int out_size)
{
    const float* inputs = (const float*)d_in[0];  // [S,B,IN]
    const float* h0     = (const float*)d_in[1];  // [B,H]
    const float* c0     = (const float*)d_in[2];  // [B,H]
    const float* W_ih   = (const float*)d_in[3];  // [4H,IN]
    const float* W_hh   = (const float*)d_in[4];  // [4H,H]
    const float* b_ih   = (const float*)d_in[5];  // [4H]
    const float* b_hh   = (const float*)d_in[6];  // [4H]
    const float* attnW  = (const float*)d_in[7];  // [S,S]
    const float* linW   = (const float*)d_in[8];  // [OUT,H]
    const float* linb   = (const float*)d_in[9];  // [OUT]
    float* out = (float*)d_out;                   // [S*B, OUT]

    void* p;
    cudaGetSymbolAddress(&p, g_Xp);    float* Xp    = (float*)p;
    cudaGetSymbolAddress(&p, g_hs);    float* hs    = (float*)p;
    cudaGetSymbolAddress(&p, g_att);   float* att   = (float*)p;
    cudaGetSymbolAddress(&p, g_gates); float* gates = (float*)p;
    cudaGetSymbolAddress(&p, g_h);     float* hbuf  = (float*)p;
    cudaGetSymbolAddress(&p, g_bias);  float* biasc = (float*)p;

    // state init + combined bias + softmax(attnW)
    init_state<<<(BATCH * HID + 255) / 256, 256>>>(h0, c0);
    bias_combine<<<(G4 + 255) / 256, 256>>>(b_ih, b_hh);
    softmax128<<<SEQ, SEQ>>>(attnW);

    // Xp[s*B+b, 4H] = X @ W_ih^T + (b_ih + b_hh)   (time-invariant, hoisted)
    {
        dim3 grid(G4 / BN, (SEQ * BATCH) / BM);
        sgemm_nt<<<grid, 128>>>(inputs, W_ih, nullptr, biasc, Xp,
                                SEQ * BATCH, G4, IND, 0, 1);
    }

    // sequential recurrence
    for (int t = 0; t < SEQ; ++t) {
        dim3 grid(G4 / BN, BATCH / BM);
        sgemm_nt<<<grid, 128>>>(hbuf, W_hh, Xp + (size_t)t * BATCH * G4, nullptr,
                                gates, BATCH, G4, HID, 1, 0);
        lstm_cell<<<(BATCH * HID) / 256, 256>>>(t);
    }

    // attention mix: att = softmax(attnW) @ hs
    {
        dim3 grid(BH / 128, SEQ / 32);
        attn_apply<<<grid, 128>>>();
    }

    // out = att @ linW^T + linb
    {
        dim3 grid(OUTD / BN, (SEQ * BATCH) / BM);
        sgemm_nt<<<grid, 128>>>(att, linW, nullptr, linb, out,
                                SEQ * BATCH, OUTD, HID, 0, 1);
    }
}

// round 4
// speedup vs baseline: 3.1689x; 3.1689x over previous
#include <cuda_runtime.h>
#include <cuda_bf16.h>
#include <math.h>
#include <stdint.h>

// Problem dims
#define SEQ   128
#define BATCH 256
#define IND   1024
#define HID   1024
#define OUTD  1024
#define G4    4096
#define BH    (BATCH*HID)
#define KP    3072            // split-bf16 K' = 3*1024
#define BK    32
#define NC    (KP/BK)         // 96 k-chunks

// ---------------- scratch (device globals) ---------------------------------
__device__ float g_Xp[(size_t)SEQ * BATCH * G4];     // 512 MB
__device__ float g_hs[(size_t)SEQ * BATCH * HID];    // 128 MB
__device__ float g_att[(size_t)SEQ * BATCH * HID];   // 128 MB
__device__ float g_gates[BATCH * G4];
__device__ float g_c[BATCH * HID];
__device__ float g_A[SEQ * SEQ];
__device__ float g_bias[G4];
__device__ __nv_bfloat16 g_Xbf[(size_t)SEQ * BATCH * KP];  // 192 MB
__device__ __nv_bfloat16 g_Wihp[(size_t)G4 * KP];
__device__ __nv_bfloat16 g_Whhp[(size_t)G4 * KP];
__device__ __nv_bfloat16 g_linWp[(size_t)OUTD * KP];
__device__ __nv_bfloat16 g_hp[(size_t)BATCH * KP];

// ---------------- PTX helpers ----------------------------------------------
__device__ __forceinline__ uint32_t smem_u32(const void* p) {
    uint32_t a;
    asm("{ .reg .u64 t; cvta.to.shared.u64 t, %1; cvt.u32.u64 %0, t; }"
        : "=r"(a) : "l"(p));
    return a;
}

#define CP_ASYNC16(dst, src) \
    asm volatile("cp.async.cg.shared.global [%0], [%1], 16;" :: "r"(dst), "l"(src))
#define CP_COMMIT()  asm volatile("cp.async.commit_group;" ::: "memory")
#define CP_WAIT1()   asm volatile("cp.async.wait_group 1;" ::: "memory")
#define CP_WAIT0()   asm volatile("cp.async.wait_group 0;" ::: "memory")

#define LDMX4(r0, r1, r2, r3, addr) \
    asm volatile("ldmatrix.sync.aligned.m8n8.x4.shared.b16 {%0,%1,%2,%3}, [%4];" \
                 : "=r"(r0), "=r"(r1), "=r"(r2), "=r"(r3) : "r"(addr))

#define MMA16816(d, a, b) \
    asm volatile("mma.sync.aligned.m16n8k16.row.col.f32.bf16.bf16.f32 " \
                 "{%0,%1,%2,%3}, {%4,%5,%6,%7}, {%8,%9}, {%0,%1,%2,%3};" \
                 : "+f"((d)[0]), "+f"((d)[1]), "+f"((d)[2]), "+f"((d)[3]) \
                 : "r"((a)[0]), "r"((a)[1]), "r"((a)[2]), "r"((a)[3]), \
                   "r"((b)[0]), "r"((b)[1]))

// swizzled 16B-chunk byte offset within a tile (row has 4 chunks of 8 bf16)
__device__ __forceinline__ uint32_t swz(int row, int c) {
    return (uint32_t)((row * 4 + (c ^ ((row >> 1) & 3))) * 16);
}

// ---------------- split-bf16 HMMA GEMM --------------------------------------
// C[M,N] = A'[M,KP] @ B'[N,KP]^T (+D)(+bias), fp32 accum.
// 256 threads = 8 warps in WGM x WGN grid. BK=32, double-buffered cp.async.
template<int BM, int BN, int WGM, int WGN>
__global__ __launch_bounds__(256)
void gemm_mma(const __nv_bfloat16* __restrict__ A,
              const __nv_bfloat16* __restrict__ B,
              const float* __restrict__ D,
              const float* __restrict__ bias,
              float* __restrict__ C,
              int N, int hasD, int hasBias)
{
    constexpr int WM = BM / WGM;           // warp tile M
    constexpr int WN = BN / WGN;           // warp tile N
    constexpr int MA = WM / 16;            // m16 atoms per warp
    constexpr int NA = WN / 8;             // n8 atoms per warp
    constexpr int A_BYTES = BM * BK * 2;   // per stage
    constexpr int B_BYTES = BN * BK * 2;
    constexpr int STAGE   = A_BYTES + B_BYTES;

    __shared__ __align__(128) char smem[2 * STAGE];
    const uint32_t sb = smem_u32(smem);

    const int tid = threadIdx.x;
    const int wid = tid >> 5;
    const int lid = tid & 31;
    const int g   = lid >> 2;
    const int tg  = lid & 3;
    const int wm  = wid / WGN;
    const int wn  = wid % WGN;
    const int bm0 = blockIdx.y * BM;
    const int bn0 = blockIdx.x * BN;

    float acc[MA][NA][4];
    #pragma unroll
    for (int i = 0; i < MA; ++i)
        #pragma unroll
        for (int j = 0; j < NA; ++j)
            #pragma unroll
            for (int q = 0; q < 4; ++q) acc[i][j][q] = 0.f;

    auto load_tile = [&](int c, int s) {
        const uint32_t abase = sb + s * STAGE;
        const uint32_t bbase = abase + A_BYTES;
        const int k0 = c * BK;
        #pragma unroll
        for (int u = tid; u < BM * 4; u += 256) {
            int r = u >> 2, cc = u & 3;
            CP_ASYNC16(abase + swz(r, cc),
                       A + (size_t)(bm0 + r) * KP + k0 + cc * 8);
        }
        #pragma unroll
        for (int u = tid; u < BN * 4; u += 256) {
            int r = u >> 2, cc = u & 3;
            CP_ASYNC16(bbase + swz(r, cc),
                       B + (size_t)(bn0 + r) * KP + k0 + cc * 8);
        }
    };

    load_tile(0, 0);
    CP_COMMIT();

    for (int c = 0; c < NC; ++c) {
        const int s = c & 1;
        if (c + 1 < NC) {
            load_tile(c + 1, s ^ 1);
            CP_COMMIT();
            CP_WAIT1();
        } else {
            CP_WAIT0();
        }
        __syncthreads();

        const uint32_t abase = sb + s * STAGE;
        const uint32_t bbase = abase + A_BYTES;

        #pragma unroll
        for (int ks = 0; ks < 2; ++ks) {
            // A fragments: one x4 per m-atom
            uint32_t afr[MA][4];
            #pragma unroll
            for (int ma = 0; ma < MA; ++ma) {
                int row = wm * WM + ma * 16 + (lid & 15);
                int cc  = 2 * ks + (lid >> 4);
                LDMX4(afr[ma][0], afr[ma][1], afr[ma][2], afr[ma][3],
                      abase + swz(row, cc));
            }
            // B fragments: one x4 per pair of n-atoms
            uint32_t bfr[NA][2];
            #pragma unroll
            for (int np = 0; np < NA / 2; ++np) {
                int row = wn * WN + np * 16 + (lid & 15);
                int cc  = 2 * ks + (lid >> 4);
                uint32_t r0, r1, r2, r3;
                LDMX4(r0, r1, r2, r3, bbase + swz(row, cc));
                bfr[2 * np + 0][0] = r0; bfr[2 * np + 1][0] = r1;
                bfr[2 * np + 0][1] = r2; bfr[2 * np + 1][1] = r3;
            }
            #pragma unroll
            for (int ma = 0; ma < MA; ++ma)
                #pragma unroll
                for (int na = 0; na < NA; ++na)
                    MMA16816(acc[ma][na], afr[ma], bfr[na]);
        }
        __syncthreads();
    }

    // Epilogue
    #pragma unroll
    for (int ma = 0; ma < MA; ++ma) {
        #pragma unroll
        for (int na = 0; na < NA; ++na) {
            const int col = bn0 + wn * WN + na * 8 + tg * 2;
            const int r0  = bm0 + wm * WM + ma * 16 + g;
            const int r1  = r0 + 8;
            float2 v0 = make_float2(acc[ma][na][0], acc[ma][na][1]);
            float2 v1 = make_float2(acc[ma][na][2], acc[ma][na][3]);
            if (hasBias) {
                float2 bv = *reinterpret_cast<const float2*>(bias + col);
                v0.x += bv.x; v0.y += bv.y; v1.x += bv.x; v1.y += bv.y;
            }
            if (hasD) {
                float2 d0 = *reinterpret_cast<const float2*>(D + (size_t)r0 * N + col);
                float2 d1 = *reinterpret_cast<const float2*>(D + (size_t)r1 * N + col);
                v0.x += d0.x; v0.y += d0.y; v1.x += d1.x; v1.y += d1.y;
            }
            *reinterpret_cast<float2*>(C + (size_t)r0 * N + col) = v0;
            *reinterpret_cast<float2*>(C + (size_t)r1 * N + col) = v1;
        }
    }
}

// ---------------- conversion kernels ---------------------------------------
// A-side layout: [hi | lo | hi] ; B-side layout: [hi | hi | lo]
__global__ void conv_A(const float* __restrict__ W, __nv_bfloat16* __restrict__ Wp, int total)
{
    int i = blockIdx.x * blockDim.x + threadIdx.x;
    if (i >= total) return;
    int r = i >> 10, k = i & 1023;
    float w = W[i];
    __nv_bfloat16 hi = __float2bfloat16(w);
    float lo = w - __bfloat162float(hi);
    size_t base = (size_t)r * KP;
    Wp[base + k]        = hi;
    Wp[base + 1024 + k] = __float2bfloat16(lo);
    Wp[base + 2048 + k] = hi;
}

__global__ void conv_B(const float* __restrict__ W, __nv_bfloat16* __restrict__ Wp, int total)
{
    int i = blockIdx.x * blockDim.x + threadIdx.x;
    if (i >= total) return;
    int r = i >> 10, k = i & 1023;
    float w = W[i];
    __nv_bfloat16 hi = __float2bfloat16(w);
    float lo = w - __bfloat162float(hi);
    size_t base = (size_t)r * KP;
    Wp[base + k]        = hi;
    Wp[base + 1024 + k] = hi;
    Wp[base + 2048 + k] = __float2bfloat16(lo);
}

__global__ void init_c(const float* __restrict__ c0)
{
    int i = blockIdx.x * blockDim.x + threadIdx.x;
    if (i < BATCH * HID) g_c[i] = c0[i];
}

__global__ void bias_combine(const float* __restrict__ b_ih, const float* __restrict__ b_hh)
{
    int i = blockIdx.x * blockDim.x + threadIdx.x;
    if (i < G4) g_bias[i] = b_ih[i] + b_hh[i];
}

__device__ __forceinline__ float sigmoidf(float x) { return 1.0f / (1.0f + expf(-x)); }

__global__ __launch_bounds__(256)
void lstm_cell(int t)
{
    int idx = blockIdx.x * blockDim.x + threadIdx.x;  // over BATCH*HID
    int b = idx >> 10;
    int j = idx & 1023;
    const float* gp = g_gates + (size_t)b * G4;
    float gi = sigmoidf(gp[j]);
    float gf = sigmoidf(gp[j + HID]);
    float gg = tanhf(gp[j + 2 * HID]);
    float go = sigmoidf(gp[j + 3 * HID]);
    float c = gf * g_c[idx] + gi * gg;
    g_c[idx] = c;
    float h = go * tanhf(c);
    g_hs[(size_t)t * BH + idx] = h;
    __nv_bfloat16 hi = __float2bfloat16(h);
    float lo = h - __bfloat162float(hi);
    size_t base = (size_t)b * KP;
    g_hp[base + j]        = hi;
    g_hp[base + 1024 + j] = __float2bfloat16(lo);
    g_hp[base + 2048 + j] = hi;
}

__global__ void softmax128(const float* __restrict__ W)
{
    int row = blockIdx.x;
    int t = threadIdx.x;
    int lane = t & 31, warp = t >> 5;
    __shared__ float red[4];
    float v = W[row * SEQ + t];

    float m = v;
    #pragma unroll
    for (int o = 16; o > 0; o >>= 1) m = fmaxf(m, __shfl_xor_sync(0xffffffffu, m, o));
    if (lane == 0) red[warp] = m;
    __syncthreads();
    m = fmaxf(fmaxf(red[0], red[1]), fmaxf(red[2], red[3]));
    __syncthreads();

    float e = expf(v - m);
    float s = e;
    #pragma unroll
    for (int o = 16; o > 0; o >>= 1) s += __shfl_xor_sync(0xffffffffu, s, o);
    if (lane == 0) red[warp] = s;
    __syncthreads();
    s = red[0] + red[1] + red[2] + red[3];
    g_A[row * SEQ + t] = e / s;
}

__global__ __launch_bounds__(128)
void attn_apply()
{
    __shared__ float Asub[32][SEQ + 1];
    const int tid = threadIdx.x;
    const int n = blockIdx.x * 128 + tid;
    const int x0 = blockIdx.y * 32;

    for (int i = tid; i < 32 * SEQ; i += 128) {
        int xx = i >> 7;
        int y = i & 127;
        Asub[xx][y] = g_A[(x0 + xx) * SEQ + y];
    }
    __syncthreads();

    float acc[32];
    #pragma unroll
    for (int xx = 0; xx < 32; ++xx) acc[xx] = 0.f;

    for (int y = 0; y < SEQ; ++y) {
        float v = g_hs[(size_t)y * BH + n];
        #pragma unroll
        for (int xx = 0; xx < 32; ++xx)
            acc[xx] = fmaf(Asub[xx][y], v, acc[xx]);
    }
    #pragma unroll
    for (int xx = 0; xx < 32; ++xx)
        g_att[(size_t)(x0 + xx) * BH + n] = acc[xx];
}

// ---------------- launch ----------------------------------------------------
extern "C" void kernel_launch(void* const* d_in, const int* in_sizes, int n_in,
                              void* d_out, int out_size)
{
    const float* inputs = (const float*)d_in[0];
    const float* h0     = (const float*)d_in[1];
    const float* c0     = (const float*)d_in[2];
    const float* W_ih   = (const float*)d_in[3];
    const float* W_hh   = (const float*)d_in[4];
    const float* b_ih   = (const float*)d_in[5];
    const float* b_hh   = (const float*)d_in[6];
    const float* attnW  = (const float*)d_in[7];
    const float* linW   = (const float*)d_in[8];
    const float* linb   = (const float*)d_in[9];
    float* out = (float*)d_out;

    void* p;
    cudaGetSymbolAddress(&p, g_Xp);    float* Xp    = (float*)p;
    cudaGetSymbolAddress(&p, g_att);   float* att   = (float*)p;
    cudaGetSymbolAddress(&p, g_gates); float* gates = (float*)p;
    cudaGetSymbolAddress(&p, g_bias);  float* biasc = (float*)p;
    cudaGetSymbolAddress(&p, g_Xbf);   __nv_bfloat16* Xbf   = (__nv_bfloat16*)p;
    cudaGetSymbolAddress(&p, g_Wihp);  __nv_bfloat16* Wihp  = (__nv_bfloat16*)p;
    cudaGetSymbolAddress(&p, g_Whhp);  __nv_bfloat16* Whhp  = (__nv_bfloat16*)p;
    cudaGetSymbolAddress(&p, g_linWp); __nv_bfloat16* linWp = (__nv_bfloat16*)p;
    cudaGetSymbolAddress(&p, g_hp);    __nv_bfloat16* hp    = (__nv_bfloat16*)p;

    // conversions + init
    conv_B<<<(G4 * 1024) / 256, 256>>>(W_ih, Wihp, G4 * 1024);
    conv_B<<<(G4 * 1024) / 256, 256>>>(W_hh, Whhp, G4 * 1024);
    conv_B<<<(OUTD * 1024) / 256, 256>>>(linW, linWp, OUTD * 1024);
    conv_A<<<(SEQ * BATCH * 1024) / 256, 256>>>(inputs, Xbf, SEQ * BATCH * 1024);
    conv_A<<<(BATCH * 1024) / 256, 256>>>(h0, hp, BATCH * 1024);
    init_c<<<(BATCH * HID + 255) / 256, 256>>>(c0);
    bias_combine<<<(G4 + 255) / 256, 256>>>(b_ih, b_hh);
    softmax128<<<SEQ, SEQ>>>(attnW);

    // Xp = X @ W_ih^T + (b_ih + b_hh)
    gemm_mma<128, 128, 2, 4><<<dim3(G4 / 128, (SEQ * BATCH) / 128), 256>>>(
        Xbf, Wihp, nullptr, biasc, Xp, G4, 0, 1);

    // sequential recurrence: gates = h @ W_hh^T + Xp[t]
    for (int t = 0; t < SEQ; ++t) {
        gemm_mma<64, 128, 2, 4><<<dim3(G4 / 128, BATCH / 64), 256>>>(
            hp, Whhp, Xp + (size_t)t * BATCH * G4, nullptr, gates, G4, 1, 0);
        lstm_cell<<<(BATCH * HID) / 256, 256>>>(t);
    }

    // attention mix
    attn_apply<<<dim3(BH / 128, SEQ / 32), 128>>>();

    // att -> att' (reuse Xbf), then out = att @ linW^T + linb
    conv_A<<<(SEQ * BATCH * 1024) / 256, 256>>>(att, Xbf, SEQ * BATCH * 1024);
    gemm_mma<128, 128, 2, 4><<<dim3(OUTD / 128, (SEQ * BATCH) / 128), 256>>>(
        Xbf, linWp, nullptr, linb, out, OUTD, 0, 1);
}